// round 17
// baseline (speedup 1.0000x reference)
#include <cuda_runtime.h>
#include <cuda_fp16.h>

#define NUM_USERS 100000
#define NUM_ITEMS 50000
#define N_NODES   150000
#define DIM       64
#define NUM_EDGES 4000000
#define ROW_CAP   96        // Poisson(26.7) bins; P(deg>96) ~ 1e-30

// Scratch (allocation-free rule: __device__ globals).
__device__ __half2 g_bufA[N_NODES * DIM / 2];   // emb_fp16, then l2
__device__ __half2 g_bufB[N_NODES * DIM / 2];   // l1
__device__ int2    g_edges[N_NODES * ROW_CAP];  // fixed-capacity row bins
__device__ int     g_cnt[N_NODES];              // degrees; zero-init, reset by
                                                // the final gather's epilogue

// -------------------------------------------------------------------------
// Kernel 1 (fully fused build): convert concat(user,item) -> fp16 bufA AND
// single-pass edge binning: slot = atomicAdd(cnt[row]), write {col<<7, val}
// into the row's fixed bin.
// -------------------------------------------------------------------------
__global__ void lgcn_build(const float* __restrict__ user_emb,
                           const float* __restrict__ item_emb,
                           const float* __restrict__ edge_vals,
                           const int*   __restrict__ edge_row,
                           const int*   __restrict__ edge_col)
{
    int i = blockIdx.x * blockDim.x + threadIdx.x;
    const int total8 = N_NODES * DIM / 8;
    if (i < total8) {
        const int user8 = NUM_USERS * DIM / 8;
        const float4* s = (i < user8)
            ? (const float4*)user_emb + 2 * (size_t)i
            : (const float4*)item_emb + 2 * (size_t)(i - user8);
        float4 a = s[0];
        float4 b = s[1];
        __half2 h0 = __floats2half2_rn(a.x, a.y);
        __half2 h1 = __floats2half2_rn(a.z, a.w);
        __half2 h2 = __floats2half2_rn(b.x, b.y);
        __half2 h3 = __floats2half2_rn(b.z, b.w);
        uint4 p;
        p.x = *(unsigned int*)&h0;
        p.y = *(unsigned int*)&h1;
        p.z = *(unsigned int*)&h2;
        p.w = *(unsigned int*)&h3;
        ((uint4*)g_bufA)[i] = p;
    }
    if (i < NUM_EDGES / 8) {
        int4   r0 = __ldcs((const int4*)edge_row + i * 2);
        int4   r1 = __ldcs((const int4*)edge_row + i * 2 + 1);
        int4   c0 = __ldcs((const int4*)edge_col + i * 2);
        int4   c1 = __ldcs((const int4*)edge_col + i * 2 + 1);
        float4 v0 = __ldcs((const float4*)edge_vals + i * 2);
        float4 v1 = __ldcs((const float4*)edge_vals + i * 2 + 1);

        int k0 = atomicAdd(&g_cnt[r0.x], 1);
        int k1 = atomicAdd(&g_cnt[r0.y], 1);
        int k2 = atomicAdd(&g_cnt[r0.z], 1);
        int k3 = atomicAdd(&g_cnt[r0.w], 1);
        int k4 = atomicAdd(&g_cnt[r1.x], 1);
        int k5 = atomicAdd(&g_cnt[r1.y], 1);
        int k6 = atomicAdd(&g_cnt[r1.z], 1);
        int k7 = atomicAdd(&g_cnt[r1.w], 1);

        // col premultiplied by row-byte-stride (128) for the gather.
        __stcs(&g_edges[(size_t)r0.x * ROW_CAP + k0],
               make_int2(c0.x << 7, __float_as_int(v0.x)));
        __stcs(&g_edges[(size_t)r0.y * ROW_CAP + k1],
               make_int2(c0.y << 7, __float_as_int(v0.y)));
        __stcs(&g_edges[(size_t)r0.z * ROW_CAP + k2],
               make_int2(c0.z << 7, __float_as_int(v0.z)));
        __stcs(&g_edges[(size_t)r0.w * ROW_CAP + k3],
               make_int2(c0.w << 7, __float_as_int(v0.w)));
        __stcs(&g_edges[(size_t)r1.x * ROW_CAP + k4],
               make_int2(c1.x << 7, __float_as_int(v1.x)));
        __stcs(&g_edges[(size_t)r1.y * ROW_CAP + k5],
               make_int2(c1.y << 7, __float_as_int(v1.y)));
        __stcs(&g_edges[(size_t)r1.z * ROW_CAP + k6],
               make_int2(c1.z << 7, __float_as_int(v1.z)));
        __stcs(&g_edges[(size_t)r1.w * ROW_CAP + k7],
               make_int2(c1.w << 7, __float_as_int(v1.w)));
    }
}

// -------------------------------------------------------------------------
// Kernel 2: warp-per-node gather, fp16 rows, STATIC inner loop: staging
// sentinel-pads all 32 smem slots ({0,0} -> reads L1-hot row 0, adds exact
// 0.0), so every chunk consumes a compile-time 16 pairs — ptxas front-
// batches all 32 row loads (MLP ~32/warp, no per-iteration guards).
// MODE 0: nxt = half(acc).
// MODE 1 (final layer fused): out = 0.25*(emb_f32 + l1 + l2 + acc);
//         also resets g_cnt[node] = 0 for the next graph replay.
// -------------------------------------------------------------------------
template<int MODE>
__global__ void __launch_bounds__(256)
lgcn_gather(const __half2* __restrict__ cur,
            __half2*       __restrict__ nxt,
            const __half2* __restrict__ l1,
            const float*   __restrict__ user_emb,
            const float*   __restrict__ item_emb,
            float*         __restrict__ out)
{
    __shared__ __align__(16) int2 s_edges[8][2][32];   // double-buffered
    const int wslot = threadIdx.x >> 5;
    const int lane  = threadIdx.x & 31;
    const int node  = blockIdx.x * 8 + wslot;
    if (node >= N_NODES) return;

    const int start = node * ROW_CAP;
    const int end   = start + g_cnt[node];
    const char* curlane = (const char*)cur + ((unsigned int)lane << 2);

    float2 acc = make_float2(0.f, 0.f);

    int buf = 0;
    for (int base = start; base < end; base += 32, buf ^= 1) {
        int idx = base + lane;
        s_edges[wslot][buf][lane] = (idx < end) ? __ldcs(&g_edges[idx])
                                                : make_int2(0, 0);
        __syncwarp();
        const int4* pe = (const int4*)&s_edges[wslot][buf][0];
        #pragma unroll
        for (int j = 0; j < 16; j++) {        // STATIC: sentinels are exact 0
            int4  e2 = pe[j];                 // edges 2j, 2j+1 (premult cols)
            float v0 = __int_as_float(e2.y);
            float v1 = __int_as_float(e2.w);
            __half2 x0 = *(const __half2*)(curlane + (unsigned int)e2.x);
            __half2 x1 = *(const __half2*)(curlane + (unsigned int)e2.z);
            float2 f0 = __half22float2(x0);
            float2 f1 = __half22float2(x1);
            acc.x = fmaf(v0, f0.x, fmaf(v1, f1.x, acc.x));
            acc.y = fmaf(v0, f0.y, fmaf(v1, f1.y, acc.y));
        }
        // next chunk stages into the other buffer; its pre-consume sync
        // orders buffer reuse two chunks apart.
    }

    if (MODE == 0) {
        nxt[(size_t)node * (DIM / 2) + lane] = __floats2half2_rn(acc.x, acc.y);
    } else {
        // Fused final combine: acc == l3 (full fp32 precision).
        const float2* e = (node < NUM_USERS)
            ? (const float2*)user_emb + (size_t)node * (DIM / 2)
            : (const float2*)item_emb + (size_t)(node - NUM_USERS) * (DIM / 2);
        float2 ev = e[lane];
        float2 f1 = __half22float2(l1[(size_t)node * (DIM / 2) + lane]);
        float2 f2 = __half22float2(cur[(size_t)node * (DIM / 2) + lane]);
        float2 r;
        r.x = (ev.x + f1.x + f2.x + acc.x) * 0.25f;
        r.y = (ev.y + f1.y + f2.y + acc.y) * 0.25f;
        ((float2*)(out + (size_t)node * DIM))[lane] = r;
        if (lane == 0) g_cnt[node] = 0;        // clean for next replay
    }
}

// -------------------------------------------------------------------------
// Launch: 4 kernels, graph-capturable, no sync, no alloc.
// -------------------------------------------------------------------------
extern "C" void kernel_launch(void* const* d_in, const int* in_sizes, int n_in,
                              void* d_out, int out_size)
{
    const float* user_emb  = (const float*)d_in[0];
    const float* item_emb  = (const float*)d_in[1];
    const float* edge_vals = (const float*)d_in[2];
    const int*   edge_row  = (const int*)d_in[3];
    const int*   edge_col  = (const int*)d_in[4];
    float* out = (float*)d_out;

    __half2 *bufA, *bufB;
    cudaGetSymbolAddress((void**)&bufA, g_bufA);
    cudaGetSymbolAddress((void**)&bufB, g_bufB);

    const int total8    = N_NODES * DIM / 8;                 // 1.2M
    const int build_grid = (total8 + 255) / 256;             // covers both roles
    const int gather_grid = (N_NODES + 7) / 8;               // 8 warps/block

    // One-pass build: fp16 embeddings + binned edge list (re-done every
    // replay; g_cnt starts zero via static init / final-gather reset).
    lgcn_build<<<build_grid, 256>>>(user_emb, item_emb,
                                    edge_vals, edge_row, edge_col);

    // Layers:  A(emb) -> B(l1) -> A(l2);  layer 3 fused with final combine.
    lgcn_gather<0><<<gather_grid, 256>>>(bufA, bufB, nullptr, nullptr, nullptr, nullptr);
    lgcn_gather<0><<<gather_grid, 256>>>(bufB, bufA, nullptr, nullptr, nullptr, nullptr);
    lgcn_gather<1><<<gather_grid, 256>>>(bufA, nullptr, bufB, user_emb, item_emb, out);
}